// round 13
// baseline (speedup 1.0000x reference)
#include <cuda_runtime.h>
#include <cuda_fp16.h>
#include <math.h>
#include <stdint.h>

// GCNII layer, folded:  M = theta*W + (1-theta)*I ;  out = S @ M + x
//   S = (1-alpha)*segment_sum(vals*x[cols], rows) + alpha*h0
// v13 = v12 resubmission (infra failure): 128-row tile, fp16 gather mirror,
// 1024 threads -> 32 warps in ONE phase-synchronized CTA/SM (occ ~50%)
// so gather latency coverage doubles WITHOUT cross-phase L2 eviction.
// Phase 2: 8x4 warp grid, m16n32 per warp, 3-pass bf16 mma.sync.

#define D 128
#define MAXN 50000
#define TILE_ROWS 128
#define THREADS 1024
#define NWARP 32
#define SSTRB 272            // smem row stride bytes: 4-bank skew, LDSM conflict-free
#define EDGE_CAP 3072        // staged edges per tile (mean 2048)

__device__ uint32_t g_Bhi[D * D / 2];
__device__ uint32_t g_Blo[D * D / 2];
__device__ uint2    g_x16[(size_t)MAXN * 32];   // x fp16: row r lane l -> [r*32+l]

// smem map (bytes)
#define SM_SHI   1024
#define SM_SLO   (1024 + 34816)
#define SM_BHI   (1024 + 2 * 34816)
#define SM_BLO   (1024 + 3 * 34816)
#define SM_ECOL  (1024 + 4 * 34816)              // 140288
#define SM_EVAL  (SM_ECOL + EDGE_CAP * 4)        // 152576
#define SM_TOTAL (SM_EVAL + EDGE_CAP * 4)        // 164864 (1 CTA/SM)

__device__ __forceinline__ uint32_t smem_u32(const void* p) {
    uint32_t a;
    asm("{ .reg .u64 t; cvta.to.shared.u64 t, %1; cvt.u32.u64 %0, t; }" : "=r"(a) : "l"(p));
    return a;
}
__device__ __forceinline__ uint32_t pack_bf16x2(float f_lo, float f_hi) {
    uint32_t r;  // upper half <- first operand
    asm("cvt.rn.bf16x2.f32 %0, %1, %2;" : "=r"(r) : "f"(f_hi), "f"(f_lo));
    return r;
}

#define LDSM_X4(r, addr)                                                      \
    asm volatile("ldmatrix.sync.aligned.m8n8.x4.shared.b16 {%0,%1,%2,%3}, [%4];" \
                 : "=r"((r)[0]), "=r"((r)[1]), "=r"((r)[2]), "=r"((r)[3])     \
                 : "r"(addr))

#define MMA(c, a, bb0, bb1)                                                   \
    asm volatile("mma.sync.aligned.m16n8k16.row.col.f32.bf16.bf16.f32 "       \
                 "{%0,%1,%2,%3}, {%4,%5,%6,%7}, {%8,%9}, {%0,%1,%2,%3};"      \
                 : "+f"((c)[0]), "+f"((c)[1]), "+f"((c)[2]), "+f"((c)[3])     \
                 : "r"((a)[0]), "r"((a)[1]), "r"((a)[2]), "r"((a)[3]),        \
                   "r"(bb0), "r"(bb1))

// fp16 edge FMA: p = uint2 of 4 halves
#define HFMA(acc, v, p) do {                                                  \
    float2 _fa = __half22float2(*(const __half2*)&(p).x);                     \
    float2 _fb = __half22float2(*(const __half2*)&(p).y);                     \
    (acc).x = fmaf((v), _fa.x, (acc).x); (acc).y = fmaf((v), _fa.y, (acc).y); \
    (acc).z = fmaf((v), _fb.x, (acc).z); (acc).w = fmaf((v), _fb.y, (acc).w); } while (0)

// ------------- prolog: x->fp16 copy + Mt=(theta*W+(1-theta)*I)^T hi/lo -----
__global__ void prolog_kernel(const float* __restrict__ x, int n4,
                              const float* __restrict__ W,
                              const float* __restrict__ lamda_p,
                              const int* __restrict__ li_p) {
    for (int t = blockIdx.x * blockDim.x + threadIdx.x; t < n4;
         t += gridDim.x * blockDim.x) {
        float4 f = ((const float4*)x)[t];
        __half2 a = __floats2half2_rn(f.x, f.y);
        __half2 b = __floats2half2_rn(f.z, f.w);
        uint2 o;
        o.x = *(const uint32_t*)&a;
        o.y = *(const uint32_t*)&b;
        g_x16[t] = o;
    }
    int t = blockIdx.x * blockDim.x + threadIdx.x;
    if (t < D * D / 2) {
        float lif = 2.0f;
        if (li_p) {
            int raw = li_p[0];
            lif = (raw >= 1 && raw <= 1000000) ? (float)raw : __int_as_float(raw);
        }
        float theta = logf(lamda_p[0] / lif + 1.0f);
        int n = t >> 6;
        int k = (t & 63) * 2;
        float v0 = theta * W[(size_t)k * D + n]       + ((n == k)     ? (1.0f - theta) : 0.f);
        float v1 = theta * W[(size_t)(k + 1) * D + n] + ((n == k + 1) ? (1.0f - theta) : 0.f);
        uint32_t hi = pack_bf16x2(v0, v1);
        float r0 = v0 - __uint_as_float(hi << 16);
        float r1 = v1 - __uint_as_float(hi & 0xffff0000u);
        g_Bhi[t] = hi;
        g_Blo[t] = pack_bf16x2(r0, r1);
    }
}

// ---------------- fused main kernel (1024 threads, 1 CTA/SM) ----------------
__global__ void __launch_bounds__(THREADS, 1)
gcn_fused_kernel(const float* __restrict__ x,
                 const float* __restrict__ h0,
                 const int*   __restrict__ rows,
                 const int*   __restrict__ cols,
                 const float* __restrict__ vals,
                 const float* __restrict__ alpha_p,
                 float* __restrict__ out,
                 int N, int E)
{
    extern __shared__ char smem[];
    int* s_rptr = (int*)smem;
    const uint32_t smb = smem_u32(smem);
    const int tid  = threadIdx.x;
    const int wid  = tid >> 5;
    const int lane = tid & 31;
    const int rowBase = blockIdx.x * TILE_ROWS;

    // ---- rowptr boundaries ----
    if (tid <= TILE_ROWS) {
        int r = rowBase + tid;
        int lo = 0, hi = E;
        while (lo < hi) {
            int m = (lo + hi) >> 1;
            if (__ldg(&rows[m]) < r) lo = m + 1; else hi = m;
        }
        s_rptr[tid] = lo;
    }
    // ---- stage Mt hi/lo into padded smem rows ----
    {
        const float4* sh = (const float4*)g_Bhi;
        const float4* sl = (const float4*)g_Blo;
        #pragma unroll
        for (int i = tid; i < 2048; i += THREADS) {
            int row = i >> 4, c16 = i & 15;
            *(float4*)(smem + SM_BHI + row * SSTRB + c16 * 16) = sh[i];
            *(float4*)(smem + SM_BLO + row * SSTRB + c16 * 16) = sl[i];
        }
    }
    __syncthreads();

    // ---- stage this tile's edge range into smem ----
    const int e0 = s_rptr[0];
    const int e1 = s_rptr[TILE_ROWS];
    const int staged = min(e1 - e0, EDGE_CAP);
    {
        int* s_ecol = (int*)(smem + SM_ECOL);
        for (int i = tid; i < staged; i += THREADS) s_ecol[i] = cols[e0 + i];
        float* s_eval = (float*)(smem + SM_EVAL);
        for (int i = tid; i < staged; i += THREADS) s_eval[i] = vals[e0 + i];
    }
    __syncthreads();

    // ---- phase 1: SpMM (fp16 gather, warp-per-row) + alpha-combine ----
    const float alpha = alpha_p[0];
    const float oma = 1.0f - alpha;
    const float4* H4 = (const float4*)h0;
    const int* s_ecol = (const int*)(smem + SM_ECOL);
    const float* s_eval = (const float*)(smem + SM_EVAL);

    for (int rr = wid; rr < TILE_ROWS; rr += NWARP) {
        int r = rowBase + rr;
        float4 acc = make_float4(0.f, 0.f, 0.f, 0.f);
        if (r < N) {
            int eb = s_rptr[rr]     - e0;
            int ee = s_rptr[rr + 1] - e0;
            if (ee <= staged) {
                int j = eb;
                for (; j + 8 <= ee; j += 8) {          // 8-wide MLP
                    uint2 p[8]; float v[8];
                    #pragma unroll
                    for (int u = 0; u < 8; ++u) {
                        int c = s_ecol[j + u];
                        p[u] = g_x16[(size_t)c * 32 + lane];
                        v[u] = s_eval[j + u];
                    }
                    #pragma unroll
                    for (int u = 0; u < 8; ++u) HFMA(acc, v[u], p[u]);
                }
                for (; j < ee; ++j) {
                    int c = s_ecol[j]; float v = s_eval[j];
                    uint2 p = g_x16[(size_t)c * 32 + lane];
                    HFMA(acc, v, p);
                }
            } else {
                for (int e = eb + e0; e < ee + e0; ++e) {
                    int c = cols[e]; float v = vals[e];
                    uint2 p = g_x16[(size_t)c * 32 + lane];
                    HFMA(acc, v, p);
                }
            }
            float4 h = H4[(size_t)r * 32 + lane];
            acc.x = fmaf(oma, acc.x, alpha * h.x);
            acc.y = fmaf(oma, acc.y, alpha * h.y);
            acc.z = fmaf(oma, acc.z, alpha * h.z);
            acc.w = fmaf(oma, acc.w, alpha * h.w);
        }
        uint32_t h01 = pack_bf16x2(acc.x, acc.y);
        uint32_t h23 = pack_bf16x2(acc.z, acc.w);
        float l0 = acc.x - __uint_as_float(h01 << 16);
        float l1 = acc.y - __uint_as_float(h01 & 0xffff0000u);
        float l2 = acc.z - __uint_as_float(h23 << 16);
        float l3 = acc.w - __uint_as_float(h23 & 0xffff0000u);
        uint32_t q01 = pack_bf16x2(l0, l1);
        uint32_t q23 = pack_bf16x2(l2, l3);
        uint32_t off = (uint32_t)(rr * SSTRB + lane * 8);
        asm volatile("st.shared.v2.b32 [%0], {%1, %2};"
                     :: "r"(smb + SM_SHI + off), "r"(h01), "r"(h23) : "memory");
        asm volatile("st.shared.v2.b32 [%0], {%1, %2};"
                     :: "r"(smb + SM_SLO + off), "r"(q01), "r"(q23) : "memory");
    }
    __syncthreads();

    // ---- phase 2: 32 warps, 8x4 grid of m16 x n32 warp tiles; 3 passes ----
    const int wm = (wid & 7) * 16;       // warp row block (0..112)
    const int wn = (wid >> 3) * 32;      // warp col block (0..96)
    const int quad = lane >> 3;
    const int l7 = lane & 7;
    const uint32_t aoff = (uint32_t)((((quad & 1) * 8) + l7) * SSTRB + (quad >> 1) * 16);
    const uint32_t boff = (uint32_t)((((quad >> 1) * 8) + l7) * SSTRB + (quad & 1) * 16);

    float acc[4][4];
    #pragma unroll
    for (int j = 0; j < 4; ++j)
        #pragma unroll
        for (int k = 0; k < 4; ++k) acc[j][k] = 0.f;

    #pragma unroll
    for (int pass = 0; pass < 3; ++pass) {
        const uint32_t Ab = smb + (pass == 2 ? SM_SLO : SM_SHI) + (uint32_t)(wm * SSTRB) + aoff;
        const uint32_t Bb = smb + (pass == 1 ? SM_BLO : SM_BHI) + (uint32_t)(wn * SSTRB) + boff;
        #pragma unroll
        for (int ks = 0; ks < 8; ++ks) {
            uint32_t a0[4], b01[4], b23[4];
            LDSM_X4(a0,  Ab + ks * 32);
            LDSM_X4(b01, Bb + ks * 32);
            LDSM_X4(b23, Bb + ks * 32 + 16 * SSTRB);
            MMA(acc[0], a0, b01[0], b01[1]);
            MMA(acc[1], a0, b01[2], b01[3]);
            MMA(acc[2], a0, b23[0], b23[1]);
            MMA(acc[3], a0, b23[2], b23[3]);
        }
    }

    // ---- epilogue: + x residual (exact fp32 x) ----
    const int g = lane >> 2, tig = lane & 3;
    #pragma unroll
    for (int half = 0; half < 2; ++half) {
        int r = rowBase + wm + half * 8 + g;
        if (r < N) {
            const float2* Xr = (const float2*)x + (size_t)r * 64;
            float2* Or = (float2*)out + (size_t)r * 64;
            #pragma unroll
            for (int nt = 0; nt < 4; ++nt) {
                int cp = (wn >> 1) + nt * 4 + tig;
                float2 xv = Xr[cp];
                float2 o;
                o.x = acc[nt][half * 2 + 0] + xv.x;
                o.y = acc[nt][half * 2 + 1] + xv.y;
                Or[cp] = o;
            }
        }
    }
}

extern "C" void kernel_launch(void* const* d_in, const int* in_sizes, int n_in,
                              void* d_out, int out_size) {
    const float* x     = (const float*)d_in[0];
    const float* h0    = (const float*)d_in[1];
    const float* W     = (const float*)d_in[2];
    const float* lamda = (const float*)d_in[3];
    const float* alpha = (const float*)d_in[4];
    const int*   arows = (const int*)d_in[5];
    const int*   acols = (const int*)d_in[6];
    const float* avals = (const float*)d_in[7];
    const int*   li    = (n_in > 8) ? (const int*)d_in[8] : nullptr;

    const int N = in_sizes[0] / D;
    const int E = in_sizes[5];
    const int n4 = min(N, MAXN) * 32;

    int pgrid = (n4 + 511) / 512;
    if (pgrid > 592) pgrid = 592;
    prolog_kernel<<<pgrid, 512>>>(x, n4, W, lamda, li);

    (void)cudaFuncSetAttribute(gcn_fused_kernel,
                               cudaFuncAttributeMaxDynamicSharedMemorySize, SM_TOTAL);
    gcn_fused_kernel<<<(N + TILE_ROWS - 1) / TILE_ROWS, THREADS, SM_TOTAL>>>(
        x, h0, arows, acols, avals, alpha, (float*)d_out, N, E);
}

// round 16
// speedup vs baseline: 1.1593x; 1.1593x over previous
#include <cuda_runtime.h>
#include <math.h>
#include <stdint.h>

// GCNII layer, folded:  M = theta*W + (1-theta)*I ;  out = S @ M + x
//   S = (1-alpha)*segment_sum(vals*x[cols], rows) + alpha*h0
// v16: TWO-KERNEL SPLIT (v14/v15 theory, perturbed to break infra flake).
//   spmm_kernel: 128 thr (4 warps), warp-per-row, 4 rows/block, tiny smem ->
//     high occupancy, fp32 gather 8-wide, S -> gmem scratch.
//   gemm_kernel: R6's validated tile GEMM (stage S -> bf16 hi/lo smem,
//     3-pass mma.sync, +x residual).

#define D 128
#define MAXN 50000
#define THREADS_S 128
#define ROWS_PER_BLK 4
#define TILE_ROWS 128
#define THREADS_G 512
#define SSTRB 272            // smem row stride: 4-bank skew, LDSM conflict-free

__device__ uint32_t g_Bhi[D * D / 2];
__device__ uint32_t g_Blo[D * D / 2];
__device__ float4   g_S[(size_t)MAXN * 32];     // S scratch: row r lane l

// gemm smem map (bytes)
#define SM_SHI   1024
#define SM_SLO   (1024 + 34816)
#define SM_BHI   (1024 + 2 * 34816)
#define SM_BLO   (1024 + 3 * 34816)
#define SM_TOTAL (1024 + 4 * 34816)   // 140288

__device__ __forceinline__ uint32_t smem_u32(const void* p) {
    uint32_t a;
    asm("{ .reg .u64 t; cvta.to.shared.u64 t, %1; cvt.u32.u64 %0, t; }" : "=r"(a) : "l"(p));
    return a;
}
__device__ __forceinline__ uint32_t pack_bf16x2(float f_lo, float f_hi) {
    uint32_t r;  // upper half <- first operand
    asm("cvt.rn.bf16x2.f32 %0, %1, %2;" : "=r"(r) : "f"(f_hi), "f"(f_lo));
    return r;
}

#define LDSM_X4(r, addr)                                                      \
    asm volatile("ldmatrix.sync.aligned.m8n8.x4.shared.b16 {%0,%1,%2,%3}, [%4];" \
                 : "=r"((r)[0]), "=r"((r)[1]), "=r"((r)[2]), "=r"((r)[3])     \
                 : "r"(addr))

#define MMA(c, a, bb0, bb1)                                                   \
    asm volatile("mma.sync.aligned.m16n8k16.row.col.f32.bf16.bf16.f32 "       \
                 "{%0,%1,%2,%3}, {%4,%5,%6,%7}, {%8,%9}, {%0,%1,%2,%3};"      \
                 : "+f"((c)[0]), "+f"((c)[1]), "+f"((c)[2]), "+f"((c)[3])     \
                 : "r"((a)[0]), "r"((a)[1]), "r"((a)[2]), "r"((a)[3]),        \
                   "r"(bb0), "r"(bb1))

#define GFMA(acc, v, p) do {                                                  \
    (acc).x = fmaf((v), (p).x, (acc).x); (acc).y = fmaf((v), (p).y, (acc).y); \
    (acc).z = fmaf((v), (p).z, (acc).z); (acc).w = fmaf((v), (p).w, (acc).w); } while (0)

// ---------------- prolog: Mt = (theta*W + (1-theta)*I)^T as bf16 hi/lo -----
__global__ void prolog_kernel(const float* __restrict__ W,
                              const float* __restrict__ lamda_p,
                              const int* __restrict__ li_p) {
    int t = blockIdx.x * blockDim.x + threadIdx.x;
    if (t >= D * D / 2) return;
    float lif = 2.0f;
    if (li_p) {
        int raw = li_p[0];
        lif = (raw >= 1 && raw <= 1000000) ? (float)raw : __int_as_float(raw);
    }
    float theta = logf(lamda_p[0] / lif + 1.0f);
    int n = t >> 6;
    int k = (t & 63) * 2;
    float v0 = theta * W[(size_t)k * D + n]       + ((n == k)     ? (1.0f - theta) : 0.f);
    float v1 = theta * W[(size_t)(k + 1) * D + n] + ((n == k + 1) ? (1.0f - theta) : 0.f);
    uint32_t hi = pack_bf16x2(v0, v1);
    float r0 = v0 - __uint_as_float(hi << 16);
    float r1 = v1 - __uint_as_float(hi & 0xffff0000u);
    g_Bhi[t] = hi;
    g_Blo[t] = pack_bf16x2(r0, r1);
}

// ---------------- SpMM kernel: high-occupancy warp-per-row gather ----------
__global__ void __launch_bounds__(THREADS_S)
spmm_kernel(const float* __restrict__ x,
            const float* __restrict__ h0,
            const int*   __restrict__ rows,
            const int*   __restrict__ cols,
            const float* __restrict__ vals,
            const float* __restrict__ alpha_p,
            int N, int E)
{
    __shared__ int s_rptr[ROWS_PER_BLK + 1];
    const int tid  = threadIdx.x;
    const int wid  = tid >> 5;
    const int lane = tid & 31;
    const int rowBase = blockIdx.x * ROWS_PER_BLK;

    if (tid <= ROWS_PER_BLK) {
        int r = rowBase + tid;
        if (r > N) r = N;
        int lo = 0, hi = E;
        while (lo < hi) {
            int m = (lo + hi) >> 1;
            if (rows[m] < r) lo = m + 1; else hi = m;
        }
        s_rptr[tid] = lo;
    }
    __syncthreads();

    const int r = rowBase + wid;
    if (r >= N) return;
    const float alpha = alpha_p[0];
    const float oma = 1.0f - alpha;
    const float4* X4 = (const float4*)x;
    const float4* H4 = (const float4*)h0;

    float4 acc = make_float4(0.f, 0.f, 0.f, 0.f);
    int e   = s_rptr[wid];
    int end = s_rptr[wid + 1];
    for (; e + 8 <= end; e += 8) {
        int c0 = cols[e],     c1 = cols[e + 1];
        int c2 = cols[e + 2], c3 = cols[e + 3];
        int c4 = cols[e + 4], c5 = cols[e + 5];
        int c6 = cols[e + 6], c7 = cols[e + 7];
        float4 p0 = X4[(size_t)c0 * 32 + lane];
        float4 p1 = X4[(size_t)c1 * 32 + lane];
        float4 p2 = X4[(size_t)c2 * 32 + lane];
        float4 p3 = X4[(size_t)c3 * 32 + lane];
        float4 p4 = X4[(size_t)c4 * 32 + lane];
        float4 p5 = X4[(size_t)c5 * 32 + lane];
        float4 p6 = X4[(size_t)c6 * 32 + lane];
        float4 p7 = X4[(size_t)c7 * 32 + lane];
        float v0 = vals[e],     v1 = vals[e + 1];
        float v2 = vals[e + 2], v3 = vals[e + 3];
        float v4 = vals[e + 4], v5 = vals[e + 5];
        float v6 = vals[e + 6], v7 = vals[e + 7];
        GFMA(acc, v0, p0); GFMA(acc, v1, p1);
        GFMA(acc, v2, p2); GFMA(acc, v3, p3);
        GFMA(acc, v4, p4); GFMA(acc, v5, p5);
        GFMA(acc, v6, p6); GFMA(acc, v7, p7);
    }
    if (e + 4 <= end) {
        int c0 = cols[e],     c1 = cols[e + 1];
        int c2 = cols[e + 2], c3 = cols[e + 3];
        float4 p0 = X4[(size_t)c0 * 32 + lane];
        float4 p1 = X4[(size_t)c1 * 32 + lane];
        float4 p2 = X4[(size_t)c2 * 32 + lane];
        float4 p3 = X4[(size_t)c3 * 32 + lane];
        float v0 = vals[e],     v1 = vals[e + 1];
        float v2 = vals[e + 2], v3 = vals[e + 3];
        GFMA(acc, v0, p0); GFMA(acc, v1, p1);
        GFMA(acc, v2, p2); GFMA(acc, v3, p3);
        e += 4;
    }
    for (; e < end; ++e) {
        int c = cols[e]; float v = vals[e];
        float4 p = X4[(size_t)c * 32 + lane];
        GFMA(acc, v, p);
    }
    float4 h = H4[(size_t)r * 32 + lane];
    acc.x = fmaf(oma, acc.x, alpha * h.x);
    acc.y = fmaf(oma, acc.y, alpha * h.y);
    acc.z = fmaf(oma, acc.z, alpha * h.z);
    acc.w = fmaf(oma, acc.w, alpha * h.w);
    g_S[(size_t)r * 32 + lane] = acc;
}

// ---------------- GEMM kernel: out = S @ Mt^T + x (R6 phase 2) -------------
__global__ void __launch_bounds__(THREADS_G, 1)
gemm_kernel(const float* __restrict__ x,
            float* __restrict__ out,
            int N)
{
    extern __shared__ char smem[];
    const uint32_t smb = smem_u32(smem);
    const int tid  = threadIdx.x;
    const int wid  = tid >> 5;
    const int lane = tid & 31;
    const int rowBase = blockIdx.x * TILE_ROWS;

    // stage Mt hi/lo into padded smem rows
    {
        const float4* sh = (const float4*)g_Bhi;
        const float4* sl = (const float4*)g_Blo;
        #pragma unroll
        for (int i = tid; i < 2048; i += THREADS_G) {
            int row = i >> 4, c16 = i & 15;
            *(float4*)(smem + SM_BHI + row * SSTRB + c16 * 16) = sh[i];
            *(float4*)(smem + SM_BLO + row * SSTRB + c16 * 16) = sl[i];
        }
    }
    // stage S tile -> bf16 hi/lo smem (warp-per-row)
    for (int rr = wid; rr < TILE_ROWS; rr += (THREADS_G / 32)) {
        int r = rowBase + rr;
        float4 acc = (r < N) ? g_S[(size_t)r * 32 + lane]
                             : make_float4(0.f, 0.f, 0.f, 0.f);
        uint32_t h01 = pack_bf16x2(acc.x, acc.y);
        uint32_t h23 = pack_bf16x2(acc.z, acc.w);
        float l0 = acc.x - __uint_as_float(h01 << 16);
        float l1 = acc.y - __uint_as_float(h01 & 0xffff0000u);
        float l2 = acc.z - __uint_as_float(h23 << 16);
        float l3 = acc.w - __uint_as_float(h23 & 0xffff0000u);
        uint32_t q01 = pack_bf16x2(l0, l1);
        uint32_t q23 = pack_bf16x2(l2, l3);
        uint32_t off = (uint32_t)(rr * SSTRB + lane * 8);
        asm volatile("st.shared.v2.b32 [%0], {%1, %2};"
                     :: "r"(smb + SM_SHI + off), "r"(h01), "r"(h23) : "memory");
        asm volatile("st.shared.v2.b32 [%0], {%1, %2};"
                     :: "r"(smb + SM_SLO + off), "r"(q01), "r"(q23) : "memory");
    }
    __syncthreads();

    // 16 warps x (32x32) warp tiles; mma.sync bf16, 3 passes
    const int wm = (wid & 3) * 32;
    const int wn = (wid >> 2) * 32;
    const int quad = lane >> 3;
    const int l7 = lane & 7;
    const uint32_t aoff = (uint32_t)((((quad & 1) * 8) + l7) * SSTRB + (quad >> 1) * 16);
    const uint32_t boff = (uint32_t)((((quad >> 1) * 8) + l7) * SSTRB + (quad & 1) * 16);

    float acc[2][4][4];
    #pragma unroll
    for (int i = 0; i < 2; ++i)
        #pragma unroll
        for (int j = 0; j < 4; ++j)
            #pragma unroll
            for (int k = 0; k < 4; ++k) acc[i][j][k] = 0.f;

    #pragma unroll
    for (int pass = 0; pass < 3; ++pass) {
        const uint32_t Ab = smb + (pass == 2 ? SM_SLO : SM_SHI) + (uint32_t)(wm * SSTRB) + aoff;
        const uint32_t Bb = smb + (pass == 1 ? SM_BLO : SM_BHI) + (uint32_t)(wn * SSTRB) + boff;
        #pragma unroll
        for (int ks = 0; ks < 8; ++ks) {
            uint32_t a0[4], a1[4], b01[4], b23[4];
            LDSM_X4(a0, Ab + ks * 32);
            LDSM_X4(a1, Ab + ks * 32 + 16 * SSTRB);
            LDSM_X4(b01, Bb + ks * 32);
            LDSM_X4(b23, Bb + ks * 32 + 16 * SSTRB);
            MMA(acc[0][0], a0, b01[0], b01[1]);
            MMA(acc[0][1], a0, b01[2], b01[3]);
            MMA(acc[0][2], a0, b23[0], b23[1]);
            MMA(acc[0][3], a0, b23[2], b23[3]);
            MMA(acc[1][0], a1, b01[0], b01[1]);
            MMA(acc[1][1], a1, b01[2], b01[3]);
            MMA(acc[1][2], a1, b23[0], b23[1]);
            MMA(acc[1][3], a1, b23[2], b23[3]);
        }
    }

    // epilogue: + x residual
    const int g = lane >> 2, tig = lane & 3;
    #pragma unroll
    for (int mt = 0; mt < 2; ++mt) {
        #pragma unroll
        for (int half = 0; half < 2; ++half) {
            int r = rowBase + wm + mt * 16 + half * 8 + g;
            if (r < N) {
                const float2* Xr = (const float2*)x + (size_t)r * 64;
                float2* Or = (float2*)out + (size_t)r * 64;
                #pragma unroll
                for (int nt = 0; nt < 4; ++nt) {
                    int cp = (wn >> 1) + nt * 4 + tig;
                    float2 xv = Xr[cp];
                    float2 o;
                    o.x = acc[mt][nt][half * 2 + 0] + xv.x;
                    o.y = acc[mt][nt][half * 2 + 1] + xv.y;
                    Or[cp] = o;
                }
            }
        }
    }
}

extern "C" void kernel_launch(void* const* d_in, const int* in_sizes, int n_in,
                              void* d_out, int out_size) {
    const float* x     = (const float*)d_in[0];
    const float* h0    = (const float*)d_in[1];
    const float* W     = (const float*)d_in[2];
    const float* lamda = (const float*)d_in[3];
    const float* alpha = (const float*)d_in[4];
    const int*   arows = (const int*)d_in[5];
    const int*   acols = (const int*)d_in[6];
    const float* avals = (const float*)d_in[7];
    const int*   li    = (n_in > 8) ? (const int*)d_in[8] : nullptr;

    const int N = in_sizes[0] / D;
    const int E = in_sizes[5];

    prolog_kernel<<<(D * D / 2 + 255) / 256, 256>>>(W, lamda, li);

    spmm_kernel<<<(N + ROWS_PER_BLK - 1) / ROWS_PER_BLK, THREADS_S>>>(
        x, h0, arows, acols, avals, alpha, N, E);

    (void)cudaFuncSetAttribute(gemm_kernel,
                               cudaFuncAttributeMaxDynamicSharedMemorySize, SM_TOTAL);
    gemm_kernel<<<(N + TILE_ROWS - 1) / TILE_ROWS, THREADS_G, SM_TOTAL>>>(
        x, (float*)d_out, N);
}